// round 9
// baseline (speedup 1.0000x reference)
#include <cuda_runtime.h>
#include <cuda_fp16.h>

#define BS   2048
#define SEQ  288
#define TST  288
#define HID  64
#define DSZ  29
#define NTHR 1024
#define NGRP 4

typedef unsigned long long u64;

__device__ __forceinline__ u64 pk2(float x, float y) {
    u64 r; asm("mov.b64 %0,{%1,%2};" : "=l"(r) : "f"(x), "f"(y)); return r;
}
__device__ __forceinline__ void upk2(u64 v, float& x, float& y) {
    asm("mov.b64 {%0,%1},%2;" : "=f"(x), "=f"(y) : "l"(v));
}
__device__ __forceinline__ u64 ffma2(u64 a, u64 b, u64 c) {
    u64 d; asm("fma.rn.f32x2 %0,%1,%2,%3;" : "=l"(d) : "l"(a), "l"(b), "l"(c)); return d;
}
__device__ __forceinline__ u64 fadd2(u64 a, u64 b) {
    u64 d; asm("add.rn.f32x2 %0,%1,%2;" : "=l"(d) : "l"(a), "l"(b)); return d;
}
__device__ __forceinline__ u64 shfl_u64(u64 v, int m) {
    float x, y; upk2(v, x, y);
    x = __shfl_xor_sync(0xffffffffu, x, m);
    y = __shfl_xor_sync(0xffffffffu, y, m);
    return pk2(x, y);
}
__device__ __forceinline__ __half2 u2h2(unsigned int v) {
    return *reinterpret_cast<__half2*>(&v);
}
__device__ __forceinline__ void gbar(int id) {
    asm volatile("bar.sync %0, 256;" :: "r"(id) : "memory");
}

// ---- SMEM layout (byte offsets) ----
// shared weights (one copy per CTA)
#define WHH_B   0                          // 192 x 128B, swizzled fp16
#define W1_B    24576                      // 32 x 128B, swizzled fp16
#define WIH_B   28672                      // 192 x 72B (36 halves, 28 used)
#define WK_B    42496                      // 64 fp32
#define BK_B    42752                      // 8 fp32
// per-group blocks (stride 1792B)
#define GRP_B   42880
#define GRP_STRIDE 1792
//   within group: GS 0(512) GXN 512(256) GHN 768(256) H32 1024(256) OUTS 1280(16)
//                 XH 1296(128, 2x32 halves) HH 1424(128) CTXH 1552(128)
#define VAL_B   (GRP_B + NGRP * GRP_STRIDE)          // 50048
#define VAL_STRIDE (SEQ * 128)                        // 36864 per group
#define SMEM_BYTES (VAL_B + NGRP * VAL_STRIDE)        // 197504

__global__ __launch_bounds__(NTHR, 1)
void decoder_persist_kernel(const float* __restrict__ xdec,
                            const float* __restrict__ enc,
                            const float* __restrict__ hid,
                            const float* __restrict__ Wih,
                            const float* __restrict__ Whh,
                            const float* __restrict__ bih,
                            const float* __restrict__ bhh,
                            const float* __restrict__ Wk,
                            const float* __restrict__ bk,
                            const float* __restrict__ W1,
                            const float* __restrict__ b1,
                            const float* __restrict__ W2,
                            const float* __restrict__ b2,
                            float* __restrict__ out)
{
    extern __shared__ char smc[];
    const int tid  = threadIdx.x;
    const int g    = tid >> 8;          // batch group 0..3
    const int gtid = tid & 255;
    const int warp = gtid >> 5;         // head / role within group
    const int lane = tid & 31;
    const int b    = blockIdx.x * NGRP + g;
    const unsigned FULL = 0xffffffffu;

    char*    grp  = smc + GRP_B + g * GRP_STRIDE;
    float*   gs   = reinterpret_cast<float*>(grp);
    float*   gxn  = reinterpret_cast<float*>(grp + 512);
    float*   ghn  = reinterpret_cast<float*>(grp + 768);
    float*   h32  = reinterpret_cast<float*>(grp + 1024);
    float*   outs = reinterpret_cast<float*>(grp + 1280);
    __half*  xh   = reinterpret_cast<__half*>(grp + 1296);
    __half*  hh   = reinterpret_cast<__half*>(grp + 1424);
    __half*  ctxh = reinterpret_cast<__half*>(grp + 1552);
    char*    valb = smc + VAL_B + g * VAL_STRIDE;
    __half*  valh = reinterpret_cast<__half*>(valb);
    const float* wks = reinterpret_cast<const float*>(smc + WK_B);
    const float* bks = reinterpret_cast<const float*>(smc + BK_B);

    // ---- per-thread constants ----
    float w28r = 0.f, w28z = 0.f, w28n = 0.f;
    float ba = 0.f, bb = 0.f, b2r = 0.f;
    if (gtid < 192) { ba = bih[gtid]; bb = bhh[gtid]; }
    else if (warp == 6) { ba = b1[lane]; bb = W2[lane]; b2r = b2[0]; }
    if (lane < 8) {
        const int i = warp * 8 + lane;
        w28r = Wih[i * DSZ + 28];
        w28z = Wih[(64 + i) * DSZ + 28];
        w28n = Wih[(128 + i) * DSZ + 28];
    }

    // ---- shared weight init (whole CTA cooperates, one copy) ----
    {
        __half* whhh = reinterpret_cast<__half*>(smc + WHH_B);
        __half* w1h  = reinterpret_cast<__half*>(smc + W1_B);
        __half* wihh = reinterpret_cast<__half*>(smc + WIH_B);
        for (int idx = tid; idx < 192 * 64; idx += NTHR) {
            int r = idx >> 6, c = idx & 63;
            whhh[r * 64 + (((c >> 3) ^ (r & 7)) << 3) + (c & 7)] = __float2half_rn(Whh[idx]);
        }
        for (int idx = tid; idx < 32 * 64; idx += NTHR) {
            int r = idx >> 6, c = idx & 63;
            w1h[r * 64 + (((c >> 3) ^ (r & 7)) << 3) + (c & 7)] = __float2half_rn(W1[idx]);
        }
        for (int idx = tid; idx < 192 * 28; idx += NTHR) {
            int r = idx / 28, k = idx - r * 28;
            wihh[r * 36 + k] = __float2half_rn(Wih[r * DSZ + k]);
        }
        if (tid < 64) reinterpret_cast<float*>(smc + WK_B)[tid] = Wk[tid];
        if (tid < 8)  reinterpret_cast<float*>(smc + BK_B)[tid] = bk[tid];
    }

    // ---- per-group state init ----
    for (int idx = gtid; idx < SEQ * 16; idx += 256) {    // val fp16 swizzled 128B rows
        int s = idx >> 4, c4 = idx & 15;
        float4 v = reinterpret_cast<const float4*>(enc + ((size_t)s * BS + b) * HID)[c4];
        int hbase = s * 64 + (((c4 >> 1) ^ (s & 7)) << 3) + ((c4 & 1) << 2);
        __half2* dst = reinterpret_cast<__half2*>(valh + hbase);
        dst[0] = __floats2half2_rn(v.x, v.y);
        dst[1] = __floats2half2_rn(v.z, v.w);
    }
    if (gtid < HID) {
        float hv = hid[(size_t)b * HID + gtid];
        h32[gtid] = hv;
        hh[gtid] = __float2half_rn(hv);
    }
    if (gtid < 28) xh[gtid] = __float2half_rn(xdec[(size_t)b * (TST + 1) * DSZ + gtid]);
    if (gtid >= 28 && gtid < 32) { xh[gtid] = __float2half_rn(0.f); xh[32 + gtid] = __float2half_rn(0.f); }
    if (gtid == 0) outs[0] = xdec[(size_t)b * (TST + 1) * DSZ + 28];

    float xv_pre = 0.f;
    if (warp == 7 && lane < 28)
        xv_pre = xdec[((size_t)b * (TST + 1) + 1) * DSZ + lane];

    __syncthreads();

#pragma unroll 1
    for (int t = 0; t < TST; ++t) {
        const int cur = t & 1, nxt = cur ^ 1;

        // ======== PHASE A: GRU dots (gw0-5) | MLP t-1 (gw6) | prefetch (gw7) ========
        if (gtid < 192) {
            const int gg = gtid >> 6, j = gtid & 63;
            const int sw = gtid & 7;
            // h-dot: Whh row (fp16 swizzled) . h (fp16)
            __half2 a0 = __floats2half2_rn(0.f, 0.f), a1 = a0, a2 = a0, a3 = a0;
            const char* wrow = smc + WHH_B + gtid * 128;
            const char* hrow = reinterpret_cast<const char*>(hh);
#pragma unroll
            for (int k = 0; k < 8; ++k) {
                uint4 wv = *reinterpret_cast<const uint4*>(wrow + ((k ^ sw) << 4));
                uint4 hv = *reinterpret_cast<const uint4*>(hrow + (k << 4));
                a0 = __hfma2(u2h2(wv.x), u2h2(hv.x), a0);
                a1 = __hfma2(u2h2(wv.y), u2h2(hv.y), a1);
                a2 = __hfma2(u2h2(wv.z), u2h2(hv.z), a2);
                a3 = __hfma2(u2h2(wv.w), u2h2(hv.w), a3);
            }
            // x-dot: Wih row (fp16 SMEM, 72B stride) . x (fp16)
            __half2 x0 = __floats2half2_rn(0.f, 0.f), x1 = x0;
            const uint2* wp = reinterpret_cast<const uint2*>(smc + WIH_B + gtid * 72);
            const uint2* xp = reinterpret_cast<const uint2*>(
                reinterpret_cast<const char*>(xh) + cur * 64);
#pragma unroll
            for (int k = 0; k < 7; ++k) {
                uint2 wv = wp[k], xv = xp[k];
                x0 = __hfma2(u2h2(wv.x), u2h2(xv.x), x0);
                x1 = __hfma2(u2h2(wv.y), u2h2(xv.y), x1);
            }
            float2 f0 = __half22float2(a0), f1 = __half22float2(a1);
            float2 f2 = __half22float2(a2), f3 = __half22float2(a3);
            float ghs = bb + ((f0.x + f0.y) + (f1.x + f1.y)) + ((f2.x + f2.y) + (f3.x + f3.y));
            float2 g0 = __half22float2(x0), g1 = __half22float2(x1);
            float gxs = ba + (g0.x + g0.y) + (g1.x + g1.y);
            if (gg < 2) gs[(gg << 6) + j] = gxs + ghs;
            else { gxn[j] = gxs; ghn[j] = ghs; }
        } else if (warp == 6) {
            if (t > 0) {
                const int sw = lane & 7;
                const char* wrow = smc + W1_B + lane * 128;
                const char* crow = reinterpret_cast<const char*>(ctxh);
                __half2 a0 = __floats2half2_rn(0.f, 0.f), a1 = a0, a2 = a0, a3 = a0;
#pragma unroll
                for (int k = 0; k < 8; ++k) {
                    uint4 wv = *reinterpret_cast<const uint4*>(wrow + ((k ^ sw) << 4));
                    uint4 cv = *reinterpret_cast<const uint4*>(crow + (k << 4));
                    a0 = __hfma2(u2h2(wv.x), u2h2(cv.x), a0);
                    a1 = __hfma2(u2h2(wv.y), u2h2(cv.y), a1);
                    a2 = __hfma2(u2h2(wv.z), u2h2(cv.z), a2);
                    a3 = __hfma2(u2h2(wv.w), u2h2(cv.w), a3);
                }
                float2 f0 = __half22float2(a0), f1 = __half22float2(a1);
                float2 f2 = __half22float2(a2), f3 = __half22float2(a3);
                float y = ba + ((f0.x + f0.y) + (f1.x + f1.y)) + ((f2.x + f2.y) + (f3.x + f3.y));
                float p = fmaxf(y, 0.f) * bb;
#pragma unroll
                for (int off = 16; off >= 1; off >>= 1)
                    p += __shfl_xor_sync(FULL, p, off);
                if (lane == 0) {
                    float o = p + b2r;
                    out[(size_t)b * TST + (t - 1)] = o;
                    outs[0] = o;
                }
            }
        } else if (warp == 7) {
            if (lane < 28) {
                xh[nxt * 32 + lane] = __float2half_rn(xv_pre);
                int row = (t + 2 <= TST) ? (t + 2) : TST;
                xv_pre = xdec[((size_t)b * (TST + 1) + row) * DSZ + lane];
            }
        }
        gbar(g + 1);

        // ======== PHASE C: gates (lanes<8) + attention (all warps, head=warp) ======
        {
            float hn = 0.f;
            if (lane < 8) {
                const int i = warp * 8 + lane;
                float o  = outs[0];
                float gr = gs[i]       + w28r * o;
                float gz = gs[64 + i]  + w28z * o;
                float ax = gxn[i]      + w28n * o;
                float ah = ghn[i];
                float r  = 1.f / (1.f + __expf(-gr));
                float z  = 1.f / (1.f + __expf(-gz));
                float a  = ax + r * ah;
                float e2 = __expf(2.f * a);
                float nt = 1.f - 2.f / (e2 + 1.f);
                float hp0 = h32[i];
                hn = nt + z * (hp0 - nt);
                h32[i] = hn;
                hh[i] = __float2half_rn(hn);
            }

            // q' = h_new @ Wk (lanes 0-7), qb = h_new . bk (lane 8)
            float q = 0.f;
#pragma unroll
            for (int d = 0; d < 8; ++d) {
                float w = (lane < 8) ? wks[d * 8 + lane]
                        : ((lane == 8) ? bks[d] : 0.f);
                q = fmaf(__shfl_sync(FULL, hn, d), w, q);
            }
            u64 qp2[4];
#pragma unroll
            for (int j = 0; j < 4; ++j)
                qp2[j] = pk2(__shfl_sync(FULL, q, 2 * j), __shfl_sync(FULL, q, 2 * j + 1));
            float qb = __shfl_sync(FULL, q, 8);

            // single-pass attention over swizzled fp16 val
            float w0 = 0.f, w1s = 0.f;
            u64 c2[4] = {0ull, 0ull, 0ull, 0ull};
            const char* vb = valb + ((warp ^ (lane & 7)) << 4) + lane * 128;
#pragma unroll
            for (int i = 0; i < 9; ++i) {
                uint4 vv = *reinterpret_cast<const uint4*>(vb + i * 4096);
                float2 f0 = __half22float2(u2h2(vv.x));
                float2 f1 = __half22float2(u2h2(vv.y));
                float2 f2 = __half22float2(u2h2(vv.z));
                float2 f3 = __half22float2(u2h2(vv.w));
                u64 v0 = pk2(f0.x, f0.y), v1 = pk2(f1.x, f1.y);
                u64 v2 = pk2(f2.x, f2.y), v3 = pk2(f3.x, f3.y);
                u64 acc = ffma2(qp2[0], v0, 0ull);
                acc = ffma2(qp2[1], v1, acc);
                acc = ffma2(qp2[2], v2, acc);
                acc = ffma2(qp2[3], v3, acc);
                float s0, s1; upk2(acc, s0, s1);
                float e = __expf(s0 + s1 + qb);
                if (i & 1) w1s += e; else w0 += e;
                u64 ee = pk2(e, e);
                c2[0] = ffma2(ee, v0, c2[0]);
                c2[1] = ffma2(ee, v1, c2[1]);
                c2[2] = ffma2(ee, v2, c2[2]);
                c2[3] = ffma2(ee, v3, c2[3]);
            }
            float wsum = w0 + w1s;

            // --- 14-shfl value-halving reduction ---
            {
                const bool hi = (lane & 16);
                u64 s0 = hi ? c2[0] : c2[2];
                u64 s1 = hi ? c2[1] : c2[3];
                u64 r0 = shfl_u64(s0, 16);
                u64 r1 = shfl_u64(s1, 16);
                u64 k0 = hi ? c2[2] : c2[0];
                u64 k1 = hi ? c2[3] : c2[1];
                c2[0] = fadd2(k0, r0);
                c2[1] = fadd2(k1, r1);
                wsum += __shfl_xor_sync(FULL, wsum, 16);
            }
            {
                const bool hi = (lane & 8);
                u64 s = hi ? c2[0] : c2[1];
                u64 r = shfl_u64(s, 8);
                u64 k = hi ? c2[1] : c2[0];
                c2[0] = fadd2(k, r);
                wsum += __shfl_xor_sync(FULL, wsum, 8);
            }
            float cv;
            {
                float lo, hi2; upk2(c2[0], lo, hi2);
                const bool hi = (lane & 4);
                float s = hi ? lo : hi2;
                float r = __shfl_xor_sync(FULL, s, 4);
                cv = (hi ? hi2 : lo) + r;
                wsum += __shfl_xor_sync(FULL, wsum, 4);
            }
            cv   += __shfl_xor_sync(FULL, cv, 2);
            wsum += __shfl_xor_sync(FULL, wsum, 2);
            cv   += __shfl_xor_sync(FULL, cv, 1);
            wsum += __shfl_xor_sync(FULL, wsum, 1);
            if ((lane & 3) == 0)
                ctxh[warp * 8 + (lane >> 2)] = __float2half_rn(cv * (1.f / wsum));
        }
        gbar(g + 1);
    }

    // final output MLP (step TST-1)
    if (warp == 6) {
        const int sw = lane & 7;
        const char* wrow = smc + W1_B + lane * 128;
        const char* crow = reinterpret_cast<const char*>(ctxh);
        __half2 a0 = __floats2half2_rn(0.f, 0.f), a1 = a0, a2 = a0, a3 = a0;
#pragma unroll
        for (int k = 0; k < 8; ++k) {
            uint4 wv = *reinterpret_cast<const uint4*>(wrow + ((k ^ sw) << 4));
            uint4 cv = *reinterpret_cast<const uint4*>(crow + (k << 4));
            a0 = __hfma2(u2h2(wv.x), u2h2(cv.x), a0);
            a1 = __hfma2(u2h2(wv.y), u2h2(cv.y), a1);
            a2 = __hfma2(u2h2(wv.z), u2h2(cv.z), a2);
            a3 = __hfma2(u2h2(wv.w), u2h2(cv.w), a3);
        }
        float2 f0 = __half22float2(a0), f1 = __half22float2(a1);
        float2 f2 = __half22float2(a2), f3 = __half22float2(a3);
        float y = ba + ((f0.x + f0.y) + (f1.x + f1.y)) + ((f2.x + f2.y) + (f3.x + f3.y));
        float p = fmaxf(y, 0.f) * bb;
#pragma unroll
        for (int off = 16; off >= 1; off >>= 1)
            p += __shfl_xor_sync(FULL, p, off);
        if (lane == 0)
            out[(size_t)b * TST + (TST - 1)] = p + b2r;
    }
}

extern "C" void kernel_launch(void* const* d_in, const int* in_sizes, int n_in,
                              void* d_out, int out_size)
{
    const float* xdec = (const float*)d_in[0];
    const float* enc  = (const float*)d_in[1];
    const float* hidp = (const float*)d_in[2];
    const float* Wih  = (const float*)d_in[3];
    const float* Whh  = (const float*)d_in[4];
    const float* bih  = (const float*)d_in[5];
    const float* bhh  = (const float*)d_in[6];
    const float* Wk   = (const float*)d_in[7];
    const float* bk   = (const float*)d_in[8];
    const float* W1   = (const float*)d_in[9];
    const float* b1   = (const float*)d_in[10];
    const float* W2   = (const float*)d_in[11];
    const float* b2   = (const float*)d_in[12];
    float* out = (float*)d_out;

    cudaFuncSetAttribute(decoder_persist_kernel,
                         cudaFuncAttributeMaxDynamicSharedMemorySize, SMEM_BYTES);
    decoder_persist_kernel<<<BS / NGRP, NTHR, SMEM_BYTES>>>(xdec, enc, hidp, Wih, Whh,
                                                            bih, bhh, Wk, bk, W1, b1,
                                                            W2, b2, out);
}

// round 10
// speedup vs baseline: 1.4004x; 1.4004x over previous
#include <cuda_runtime.h>
#include <cuda_fp16.h>

#define BS   2048
#define SEQ  288
#define TST  288
#define HID  64
#define DSZ  29
#define NTHR 256

typedef unsigned long long u64;

__device__ __forceinline__ u64 pk2(float x, float y) {
    u64 r; asm("mov.b64 %0,{%1,%2};" : "=l"(r) : "f"(x), "f"(y)); return r;
}
__device__ __forceinline__ void upk2(u64 v, float& x, float& y) {
    asm("mov.b64 {%0,%1},%2;" : "=f"(x), "=f"(y) : "l"(v));
}
__device__ __forceinline__ u64 fadd2(u64 a, u64 b) {
    u64 d; asm("add.rn.f32x2 %0,%1,%2;" : "=l"(d) : "l"(a), "l"(b)); return d;
}
__device__ __forceinline__ u64 shfl_u64(u64 v, int m) {
    float x, y; upk2(v, x, y);
    x = __shfl_xor_sync(0xffffffffu, x, m);
    y = __shfl_xor_sync(0xffffffffu, y, m);
    return pk2(x, y);
}
__device__ __forceinline__ __half2 u2h2(unsigned int v) {
    return *reinterpret_cast<__half2*>(&v);
}

// ---- SMEM layout (byte offsets) ----
#define GS_B    0                         // 128 fp32: gx+gh (r rows 0-63, z rows 64-127)
#define GXN_B   512                       // 64 fp32
#define GHN_B   768                       // 64 fp32
#define H32_B   1024                      // 64 fp32
#define OUTS_B  1280                      // 1 fp32
#define XH_B    1312                      // 2 x 32 halves (double buffer)
#define HH_B    1440                      // 64 halves
#define CTXH_B  1568                      // 64 halves
#define VAL_B   1792                      // 288 rows x 128B, swizzled
#define WHH_B   (VAL_B + SEQ * 128)       // 38656: 192 rows x 128B, swizzled
#define W1_B    (WHH_B + 192 * 128)       // 63232: 32 rows x 128B, swizzled
#define SMEM_BYTES (W1_B + 32 * 128)      // 67328

__global__ __launch_bounds__(NTHR, 3)
void decoder_persist_kernel(const float* __restrict__ xdec,
                            const float* __restrict__ enc,
                            const float* __restrict__ hid,
                            const float* __restrict__ Wih,
                            const float* __restrict__ Whh,
                            const float* __restrict__ bih,
                            const float* __restrict__ bhh,
                            const float* __restrict__ Wk,
                            const float* __restrict__ bk,
                            const float* __restrict__ W1,
                            const float* __restrict__ b1,
                            const float* __restrict__ W2,
                            const float* __restrict__ b2,
                            float* __restrict__ out)
{
    extern __shared__ char smc[];
    float*   sm32 = reinterpret_cast<float*>(smc);
    __half*  xh   = reinterpret_cast<__half*>(smc + XH_B);
    __half*  hh   = reinterpret_cast<__half*>(smc + HH_B);
    __half*  ctxh = reinterpret_cast<__half*>(smc + CTXH_B);
    __half*  valh = reinterpret_cast<__half*>(smc + VAL_B);
    __half*  whhh = reinterpret_cast<__half*>(smc + WHH_B);
    __half*  w1h  = reinterpret_cast<__half*>(smc + W1_B);

    const int tid  = threadIdx.x;
    const int warp = tid >> 5;      // head id in phase C
    const int lane = tid & 31;
    const int b    = blockIdx.x;
    const unsigned FULL = 0xffffffffu;

    // ---- register-resident constants ----
    __half2 wih2[16];               // Wih row cols 0..31 (pad 28..31 = 0), tid<192
    float wk[8];                    // Wk column (lanes 0-7), else 0 (bk dropped: softmax-invariant)
    float w28r = 0.f, w28z = 0.f, w28n = 0.f;
    float ba = 0.f, bb = 0.f;       // bih/bhh (tid<192); b1/W2 (warp 6)
    float b2r = 0.f;

    if (tid < 192) {
        const float* wr = Wih + tid * DSZ;
#pragma unroll
        for (int j = 0; j < 14; ++j) wih2[j] = __floats2half2_rn(wr[2*j], wr[2*j+1]);
        wih2[14] = __floats2half2_rn(0.f, 0.f);
        wih2[15] = wih2[14];
        ba = bih[tid]; bb = bhh[tid];
    } else if (warp == 6) {
        ba = b1[lane]; bb = W2[lane]; b2r = b2[0];
    }
#pragma unroll
    for (int d = 0; d < 8; ++d)
        wk[d] = (lane < 8) ? Wk[d * 8 + lane] : 0.f;
    if (lane < 8) {
        const int i = warp * 8 + lane;
        w28r = Wih[i * DSZ + 28];
        w28z = Wih[(64 + i) * DSZ + 28];
        w28n = Wih[(128 + i) * DSZ + 28];
    }

    // ---- SMEM init ----
    for (int idx = tid; idx < SEQ * 16; idx += NTHR) {     // val fp16 swizzled 128B rows
        int s = idx >> 4, c4 = idx & 15;
        float4 v = reinterpret_cast<const float4*>(enc + ((size_t)s * BS + b) * HID)[c4];
        int hbase = s * 64 + (((c4 >> 1) ^ (s & 7)) << 3) + ((c4 & 1) << 2);
        __half2* dst = reinterpret_cast<__half2*>(valh + hbase);
        dst[0] = __floats2half2_rn(v.x, v.y);
        dst[1] = __floats2half2_rn(v.z, v.w);
    }
    for (int idx = tid; idx < 192 * 64; idx += NTHR) {     // Whh fp16 swizzled
        int r = idx >> 6, c = idx & 63;
        whhh[r * 64 + (((c >> 3) ^ (r & 7)) << 3) + (c & 7)] = __float2half_rn(Whh[idx]);
    }
    for (int idx = tid; idx < 32 * 64; idx += NTHR) {      // W1 fp16 swizzled
        int r = idx >> 6, c = idx & 63;
        w1h[r * 64 + (((c >> 3) ^ (r & 7)) << 3) + (c & 7)] = __float2half_rn(W1[idx]);
    }
    if (tid < HID) {
        float hv = hid[(size_t)b * HID + tid];
        sm32[(H32_B >> 2) + tid] = hv;
        hh[tid] = __float2half_rn(hv);
    }
    if (tid < 28) xh[tid] = __float2half_rn(xdec[(size_t)b * (TST + 1) * DSZ + tid]);
    if (tid >= 28 && tid < 32) { xh[tid] = __float2half_rn(0.f); xh[32 + tid] = __float2half_rn(0.f); }
    const float o0 = xdec[(size_t)b * (TST + 1) * DSZ + 28];
    if (tid == 0) sm32[OUTS_B >> 2] = o0;

    float xv_pre = 0.f;
    if (warp == 7 && lane < 28)
        xv_pre = xdec[((size_t)b * (TST + 1) + 1) * DSZ + lane];

    __syncthreads();

#pragma unroll 1
    for (int t = 0; t < TST; ++t) {
        const int cur = t & 1, nxt = cur ^ 1;

        // ======== PHASE A: GRU dots (w0-5) | MLP t-1 (w6) | prefetch (w7) ========
        if (tid < 192) {
            const int g = tid >> 6, j = tid & 63;
            const int sw = tid & 7;
            __half2 a0 = __floats2half2_rn(0.f, 0.f), a1 = a0, a2 = a0, a3 = a0;
            const char* wrow = smc + WHH_B + tid * 128;
#pragma unroll
            for (int k = 0; k < 8; ++k) {
                uint4 wv = *reinterpret_cast<const uint4*>(wrow + ((k ^ sw) << 4));
                uint4 hv = *reinterpret_cast<const uint4*>(smc + HH_B + (k << 4));
                a0 = __hfma2(u2h2(wv.x), u2h2(hv.x), a0);
                a1 = __hfma2(u2h2(wv.y), u2h2(hv.y), a1);
                a2 = __hfma2(u2h2(wv.z), u2h2(hv.z), a2);
                a3 = __hfma2(u2h2(wv.w), u2h2(hv.w), a3);
            }
            __half2 x0 = __floats2half2_rn(0.f, 0.f), x1 = x0;
            const char* xrow = smc + XH_B + cur * 64;
#pragma unroll
            for (int k = 0; k < 4; ++k) {
                uint4 xv = *reinterpret_cast<const uint4*>(xrow + (k << 4));
                x0 = __hfma2(wih2[4*k+0], u2h2(xv.x), x0);
                x1 = __hfma2(wih2[4*k+1], u2h2(xv.y), x1);
                x0 = __hfma2(wih2[4*k+2], u2h2(xv.z), x0);
                x1 = __hfma2(wih2[4*k+3], u2h2(xv.w), x1);
            }
            float2 f0 = __half22float2(a0), f1 = __half22float2(a1);
            float2 f2 = __half22float2(a2), f3 = __half22float2(a3);
            float ghs = bb + ((f0.x + f0.y) + (f1.x + f1.y)) + ((f2.x + f2.y) + (f3.x + f3.y));
            float2 g0 = __half22float2(x0), g1 = __half22float2(x1);
            float gxs = ba + (g0.x + g0.y) + (g1.x + g1.y);
            if (g < 2) sm32[(GS_B >> 2) + (g << 6) + j] = gxs + ghs;
            else { sm32[(GXN_B >> 2) + j] = gxs; sm32[(GHN_B >> 2) + j] = ghs; }
        } else if (warp == 6) {
            if (t > 0) {
                const int sw = lane & 7;
                const char* wrow = smc + W1_B + lane * 128;
                __half2 a0 = __floats2half2_rn(0.f, 0.f), a1 = a0, a2 = a0, a3 = a0;
#pragma unroll
                for (int k = 0; k < 8; ++k) {
                    uint4 wv = *reinterpret_cast<const uint4*>(wrow + ((k ^ sw) << 4));
                    uint4 cv = *reinterpret_cast<const uint4*>(smc + CTXH_B + (k << 4));
                    a0 = __hfma2(u2h2(wv.x), u2h2(cv.x), a0);
                    a1 = __hfma2(u2h2(wv.y), u2h2(cv.y), a1);
                    a2 = __hfma2(u2h2(wv.z), u2h2(cv.z), a2);
                    a3 = __hfma2(u2h2(wv.w), u2h2(cv.w), a3);
                }
                float2 f0 = __half22float2(a0), f1 = __half22float2(a1);
                float2 f2 = __half22float2(a2), f3 = __half22float2(a3);
                float y = ba + ((f0.x + f0.y) + (f1.x + f1.y)) + ((f2.x + f2.y) + (f3.x + f3.y));
                float p = fmaxf(y, 0.f) * bb;
#pragma unroll
                for (int off = 16; off >= 1; off >>= 1)
                    p += __shfl_xor_sync(FULL, p, off);
                if (lane == 0) {
                    float o = p + b2r;
                    out[(size_t)b * TST + (t - 1)] = o;
                    sm32[OUTS_B >> 2] = o;
                }
            }
        } else if (warp == 7) {
            if (lane < 28) {
                xh[nxt * 32 + lane] = __float2half_rn(xv_pre);
                int row = (t + 2 <= TST) ? (t + 2) : TST;
                xv_pre = xdec[((size_t)b * (TST + 1) + row) * DSZ + lane];
            }
        }
        __syncthreads();

        // ======== PHASE C: gates (lanes<8) + attention (all warps, head=warp) ======
        {
            float hn = 0.f;
            if (lane < 8) {
                const int i = warp * 8 + lane;
                float o  = sm32[OUTS_B >> 2];
                float gr = sm32[(GS_B >> 2) + i]      + w28r * o;
                float gz = sm32[(GS_B >> 2) + 64 + i] + w28z * o;
                float ax = sm32[(GXN_B >> 2) + i]     + w28n * o;
                float ah = sm32[(GHN_B >> 2) + i];
                float r  = 1.f / (1.f + __expf(-gr));
                float z  = 1.f / (1.f + __expf(-gz));
                float a  = ax + r * ah;
                float e2 = __expf(2.f * a);
                float nt = 1.f - 2.f / (e2 + 1.f);
                float hp0 = sm32[(H32_B >> 2) + i];
                hn = nt + z * (hp0 - nt);
                sm32[(H32_B >> 2) + i] = hn;
                hh[i] = __float2half_rn(hn);
            }

            // q' = h_new @ Wk (lanes 0-7); bk dropped (softmax-invariant)
            float q = 0.f;
#pragma unroll
            for (int d = 0; d < 8; ++d)
                q = fmaf(__shfl_sync(FULL, hn, d), wk[d], q);
            __half2 qh[4];
#pragma unroll
            for (int j = 0; j < 4; ++j)
                qh[j] = __floats2half2_rn(__shfl_sync(FULL, q, 2 * j),
                                          __shfl_sync(FULL, q, 2 * j + 1));

            // single-pass attention over swizzled fp16 val (fp16 accumulation)
            float w0 = 0.f, w1s = 0.f;
            __half2 hz = __floats2half2_rn(0.f, 0.f);
            __half2 c0 = hz, c1 = hz, c2h = hz, c3 = hz;
            const char* vb = smc + VAL_B + ((warp ^ (lane & 7)) << 4) + lane * 128;
#pragma unroll
            for (int i = 0; i < 9; ++i) {
                uint4 vv = *reinterpret_cast<const uint4*>(vb + i * 4096);
                __half2 v0 = u2h2(vv.x), v1 = u2h2(vv.y), v2 = u2h2(vv.z), v3 = u2h2(vv.w);
                __half2 s = __hmul2(qh[0], v0);
                s = __hfma2(qh[1], v1, s);
                s = __hfma2(qh[2], v2, s);
                s = __hfma2(qh[3], v3, s);
                float2 sf = __half22float2(s);
                float e = __expf(sf.x + sf.y);
                if (i & 1) w1s += e; else w0 += e;
                __half2 eh = __float2half2_rn(e);
                c0 = __hfma2(eh, v0, c0);
                c1 = __hfma2(eh, v1, c1);
                c2h = __hfma2(eh, v2, c2h);
                c3 = __hfma2(eh, v3, c3);
            }
            float wsum = w0 + w1s;
            // convert ctx accumulators to fp32 once, then fp32 reduction
            float2 d0 = __half22float2(c0), d1 = __half22float2(c1);
            float2 d2 = __half22float2(c2h), d3 = __half22float2(c3);
            u64 c2[4] = { pk2(d0.x, d0.y), pk2(d1.x, d1.y),
                          pk2(d2.x, d2.y), pk2(d3.x, d3.y) };

            // --- 14-shfl value-halving reduction ---
            {
                const bool hi = (lane & 16);
                u64 s0 = hi ? c2[0] : c2[2];
                u64 s1 = hi ? c2[1] : c2[3];
                u64 r0 = shfl_u64(s0, 16);
                u64 r1 = shfl_u64(s1, 16);
                u64 k0 = hi ? c2[2] : c2[0];
                u64 k1 = hi ? c2[3] : c2[1];
                c2[0] = fadd2(k0, r0);
                c2[1] = fadd2(k1, r1);
                wsum += __shfl_xor_sync(FULL, wsum, 16);
            }
            {
                const bool hi = (lane & 8);
                u64 s = hi ? c2[0] : c2[1];
                u64 r = shfl_u64(s, 8);
                u64 k = hi ? c2[1] : c2[0];
                c2[0] = fadd2(k, r);
                wsum += __shfl_xor_sync(FULL, wsum, 8);
            }
            float cv;
            {
                float lo, hi2; upk2(c2[0], lo, hi2);
                const bool hi = (lane & 4);
                float s = hi ? lo : hi2;
                float r = __shfl_xor_sync(FULL, s, 4);
                cv = (hi ? hi2 : lo) + r;
                wsum += __shfl_xor_sync(FULL, wsum, 4);
            }
            cv   += __shfl_xor_sync(FULL, cv, 2);
            wsum += __shfl_xor_sync(FULL, wsum, 2);
            cv   += __shfl_xor_sync(FULL, cv, 1);
            wsum += __shfl_xor_sync(FULL, wsum, 1);
            if ((lane & 3) == 0)
                ctxh[warp * 8 + (lane >> 2)] = __float2half_rn(cv * (1.f / wsum));
        }
        __syncthreads();
    }

    // final output MLP (step TST-1)
    if (warp == 6) {
        const int sw = lane & 7;
        const char* wrow = smc + W1_B + lane * 128;
        __half2 a0 = __floats2half2_rn(0.f, 0.f), a1 = a0, a2 = a0, a3 = a0;
#pragma unroll
        for (int k = 0; k < 8; ++k) {
            uint4 wv = *reinterpret_cast<const uint4*>(wrow + ((k ^ sw) << 4));
            uint4 cv = *reinterpret_cast<const uint4*>(smc + CTXH_B + (k << 4));
            a0 = __hfma2(u2h2(wv.x), u2h2(cv.x), a0);
            a1 = __hfma2(u2h2(wv.y), u2h2(cv.y), a1);
            a2 = __hfma2(u2h2(wv.z), u2h2(cv.z), a2);
            a3 = __hfma2(u2h2(wv.w), u2h2(cv.w), a3);
        }
        float2 f0 = __half22float2(a0), f1 = __half22float2(a1);
        float2 f2 = __half22float2(a2), f3 = __half22float2(a3);
        float y = ba + ((f0.x + f0.y) + (f1.x + f1.y)) + ((f2.x + f2.y) + (f3.x + f3.y));
        float p = fmaxf(y, 0.f) * bb;
#pragma unroll
        for (int off = 16; off >= 1; off >>= 1)
            p += __shfl_xor_sync(FULL, p, off);
        if (lane == 0)
            out[(size_t)b * TST + (TST - 1)] = p + b2r;
    }
}

extern "C" void kernel_launch(void* const* d_in, const int* in_sizes, int n_in,
                              void* d_out, int out_size)
{
    const float* xdec = (const float*)d_in[0];
    const float* enc  = (const float*)d_in[1];
    const float* hidp = (const float*)d_in[2];
    const float* Wih  = (const float*)d_in[3];
    const float* Whh  = (const float*)d_in[4];
    const float* bih  = (const float*)d_in[5];
    const float* bhh  = (const float*)d_in[6];
    const float* Wk   = (const float*)d_in[7];
    const float* bk   = (const float*)d_in[8];
    const float* W1   = (const float*)d_in[9];
    const float* b1   = (const float*)d_in[10];
    const float* W2   = (const float*)d_in[11];
    const float* b2   = (const float*)d_in[12];
    float* out = (float*)d_out;

    cudaFuncSetAttribute(decoder_persist_kernel,
                         cudaFuncAttributeMaxDynamicSharedMemorySize, SMEM_BYTES);
    decoder_persist_kernel<<<BS, NTHR, SMEM_BYTES>>>(xdec, enc, hidp, Wih, Whh, bih, bhh,
                                                     Wk, bk, W1, b1, W2, b2, out);
}

// round 11
// speedup vs baseline: 1.4315x; 1.0222x over previous
#include <cuda_runtime.h>
#include <cuda_fp16.h>

#define BS   2048
#define SEQ  288
#define TST  288
#define HID  64
#define DSZ  29
#define NTHR 256

typedef unsigned long long u64;

__device__ __forceinline__ u64 pk2(float x, float y) {
    u64 r; asm("mov.b64 %0,{%1,%2};" : "=l"(r) : "f"(x), "f"(y)); return r;
}
__device__ __forceinline__ void upk2(u64 v, float& x, float& y) {
    asm("mov.b64 {%0,%1},%2;" : "=f"(x), "=f"(y) : "l"(v));
}
__device__ __forceinline__ u64 fadd2(u64 a, u64 b) {
    u64 d; asm("add.rn.f32x2 %0,%1,%2;" : "=l"(d) : "l"(a), "l"(b)); return d;
}
__device__ __forceinline__ u64 shfl_u64(u64 v, int m) {
    float x, y; upk2(v, x, y);
    x = __shfl_xor_sync(0xffffffffu, x, m);
    y = __shfl_xor_sync(0xffffffffu, y, m);
    return pk2(x, y);
}
__device__ __forceinline__ __half2 u2h2(unsigned int v) {
    return *reinterpret_cast<__half2*>(&v);
}

// ---- SMEM layout (byte offsets) ----
#define GS_B    0                         // 128 fp32: gx+gh (r rows 0-63, z rows 64-127)
#define GXN_B   512                       // 64 fp32
#define GHN_B   768                       // 64 fp32
#define H32_B   1024                      // 64 fp32
#define OUTS_B  1280                      // 1 fp32
#define XH_B    1312                      // 2 x 32 halves (double buffer)
#define HH_B    1440                      // 64 halves
#define CTXH_B  1568                      // 64 halves
#define QH_B    1696                      // 8 warps x 8 halves (16B each)
#define VAL_B   1920                      // 288 rows x 128B, swizzled (128-aligned)
#define WHH_B   (VAL_B + SEQ * 128)       // 192 rows x 128B, swizzled
#define W1_B    (WHH_B + 192 * 128)       // 32 rows x 128B, swizzled
#define SMEM_BYTES (W1_B + 32 * 128)      // 67456

__global__ __launch_bounds__(NTHR, 3)
void decoder_persist_kernel(const float* __restrict__ xdec,
                            const float* __restrict__ enc,
                            const float* __restrict__ hid,
                            const float* __restrict__ Wih,
                            const float* __restrict__ Whh,
                            const float* __restrict__ bih,
                            const float* __restrict__ bhh,
                            const float* __restrict__ Wk,
                            const float* __restrict__ bk,
                            const float* __restrict__ W1,
                            const float* __restrict__ b1,
                            const float* __restrict__ W2,
                            const float* __restrict__ b2,
                            float* __restrict__ out)
{
    extern __shared__ char smc[];
    float*   sm32 = reinterpret_cast<float*>(smc);
    __half*  xh   = reinterpret_cast<__half*>(smc + XH_B);
    __half*  hh   = reinterpret_cast<__half*>(smc + HH_B);
    __half*  ctxh = reinterpret_cast<__half*>(smc + CTXH_B);
    __half*  qsm  = reinterpret_cast<__half*>(smc + QH_B);
    __half*  valh = reinterpret_cast<__half*>(smc + VAL_B);
    __half*  whhh = reinterpret_cast<__half*>(smc + WHH_B);
    __half*  w1h  = reinterpret_cast<__half*>(smc + W1_B);

    const int tid  = threadIdx.x;
    const int warp = tid >> 5;      // head id in phase C
    const int lane = tid & 31;
    const int b    = blockIdx.x;
    const unsigned FULL = 0xffffffffu;

    // ---- register-resident constants ----
    __half2 wih2[16];               // Wih row cols 0..31 (pad 28..31 = 0), tid<192
    float wk[8];                    // Wk column (lanes 0-7); bk dropped (softmax-invariant)
    float w28r = 0.f, w28z = 0.f, w28n = 0.f;
    float ba = 0.f, bb = 0.f;       // bih/bhh (tid<192); b1/W2 (warp 6)
    float b2r = 0.f;

    if (tid < 192) {
        const float* wr = Wih + tid * DSZ;
#pragma unroll
        for (int j = 0; j < 14; ++j) wih2[j] = __floats2half2_rn(wr[2*j], wr[2*j+1]);
        wih2[14] = __floats2half2_rn(0.f, 0.f);
        wih2[15] = wih2[14];
        ba = bih[tid]; bb = bhh[tid];
    } else if (warp == 6) {
        ba = b1[lane]; bb = W2[lane]; b2r = b2[0];
    }
#pragma unroll
    for (int d = 0; d < 8; ++d)
        wk[d] = (lane < 8) ? Wk[d * 8 + lane] : 0.f;
    if (lane < 8) {
        const int i = warp * 8 + lane;
        w28r = Wih[i * DSZ + 28];
        w28z = Wih[(64 + i) * DSZ + 28];
        w28n = Wih[(128 + i) * DSZ + 28];
    }

    // ---- SMEM init ----
    for (int idx = tid; idx < SEQ * 16; idx += NTHR) {     // val fp16 swizzled 128B rows
        int s = idx >> 4, c4 = idx & 15;
        float4 v = reinterpret_cast<const float4*>(enc + ((size_t)s * BS + b) * HID)[c4];
        int hbase = s * 64 + (((c4 >> 1) ^ (s & 7)) << 3) + ((c4 & 1) << 2);
        __half2* dst = reinterpret_cast<__half2*>(valh + hbase);
        dst[0] = __floats2half2_rn(v.x, v.y);
        dst[1] = __floats2half2_rn(v.z, v.w);
    }
    for (int idx = tid; idx < 192 * 64; idx += NTHR) {     // Whh fp16 swizzled
        int r = idx >> 6, c = idx & 63;
        whhh[r * 64 + (((c >> 3) ^ (r & 7)) << 3) + (c & 7)] = __float2half_rn(Whh[idx]);
    }
    for (int idx = tid; idx < 32 * 64; idx += NTHR) {      // W1 fp16 swizzled
        int r = idx >> 6, c = idx & 63;
        w1h[r * 64 + (((c >> 3) ^ (r & 7)) << 3) + (c & 7)] = __float2half_rn(W1[idx]);
    }
    if (tid < HID) {
        float hv = hid[(size_t)b * HID + tid];
        sm32[(H32_B >> 2) + tid] = hv;
        hh[tid] = __float2half_rn(hv);
    }
    if (tid < 28) xh[tid] = __float2half_rn(xdec[(size_t)b * (TST + 1) * DSZ + tid]);
    if (tid >= 28 && tid < 32) { xh[tid] = __float2half_rn(0.f); xh[32 + tid] = __float2half_rn(0.f); }
    const float o0 = xdec[(size_t)b * (TST + 1) * DSZ + 28];
    if (tid == 0) sm32[OUTS_B >> 2] = o0;

    float xv_pre = 0.f;
    if (warp == 7 && lane < 28)
        xv_pre = xdec[((size_t)b * (TST + 1) + 1) * DSZ + lane];

    __syncthreads();

#pragma unroll 1
    for (int t = 0; t < TST; ++t) {
        const int cur = t & 1, nxt = cur ^ 1;

        // ======== PHASE A: GRU dots (w0-5) | MLP t-1 (w6) | prefetch (w7) ========
        if (tid < 192) {
            const int g = tid >> 6, j = tid & 63;
            const int sw = tid & 7;
            __half2 a0 = __floats2half2_rn(0.f, 0.f), a1 = a0, a2 = a0, a3 = a0;
            const char* wrow = smc + WHH_B + tid * 128;
#pragma unroll
            for (int k = 0; k < 8; ++k) {
                uint4 wv = *reinterpret_cast<const uint4*>(wrow + ((k ^ sw) << 4));
                uint4 hv = *reinterpret_cast<const uint4*>(smc + HH_B + (k << 4));
                a0 = __hfma2(u2h2(wv.x), u2h2(hv.x), a0);
                a1 = __hfma2(u2h2(wv.y), u2h2(hv.y), a1);
                a2 = __hfma2(u2h2(wv.z), u2h2(hv.z), a2);
                a3 = __hfma2(u2h2(wv.w), u2h2(hv.w), a3);
            }
            __half2 x0 = __floats2half2_rn(0.f, 0.f), x1 = x0;
            const char* xrow = smc + XH_B + cur * 64;
#pragma unroll
            for (int k = 0; k < 4; ++k) {
                uint4 xv = *reinterpret_cast<const uint4*>(xrow + (k << 4));
                x0 = __hfma2(wih2[4*k+0], u2h2(xv.x), x0);
                x1 = __hfma2(wih2[4*k+1], u2h2(xv.y), x1);
                x0 = __hfma2(wih2[4*k+2], u2h2(xv.z), x0);
                x1 = __hfma2(wih2[4*k+3], u2h2(xv.w), x1);
            }
            float2 f0 = __half22float2(a0), f1 = __half22float2(a1);
            float2 f2 = __half22float2(a2), f3 = __half22float2(a3);
            float ghs = bb + ((f0.x + f0.y) + (f1.x + f1.y)) + ((f2.x + f2.y) + (f3.x + f3.y));
            float2 g0 = __half22float2(x0), g1 = __half22float2(x1);
            float gxs = ba + (g0.x + g0.y) + (g1.x + g1.y);
            if (g < 2) sm32[(GS_B >> 2) + (g << 6) + j] = gxs + ghs;
            else { sm32[(GXN_B >> 2) + j] = gxs; sm32[(GHN_B >> 2) + j] = ghs; }
        } else if (warp == 6) {
            if (t > 0) {
                const int sw = lane & 7;
                const char* wrow = smc + W1_B + lane * 128;
                __half2 a0 = __floats2half2_rn(0.f, 0.f), a1 = a0, a2 = a0, a3 = a0;
#pragma unroll
                for (int k = 0; k < 8; ++k) {
                    uint4 wv = *reinterpret_cast<const uint4*>(wrow + ((k ^ sw) << 4));
                    uint4 cv = *reinterpret_cast<const uint4*>(smc + CTXH_B + (k << 4));
                    a0 = __hfma2(u2h2(wv.x), u2h2(cv.x), a0);
                    a1 = __hfma2(u2h2(wv.y), u2h2(cv.y), a1);
                    a2 = __hfma2(u2h2(wv.z), u2h2(cv.z), a2);
                    a3 = __hfma2(u2h2(wv.w), u2h2(cv.w), a3);
                }
                float2 f0 = __half22float2(a0), f1 = __half22float2(a1);
                float2 f2 = __half22float2(a2), f3 = __half22float2(a3);
                float y = ba + ((f0.x + f0.y) + (f1.x + f1.y)) + ((f2.x + f2.y) + (f3.x + f3.y));
                float p = fmaxf(y, 0.f) * bb;
#pragma unroll
                for (int off = 16; off >= 1; off >>= 1)
                    p += __shfl_xor_sync(FULL, p, off);
                if (lane == 0) {
                    float o = p + b2r;
                    out[(size_t)b * TST + (t - 1)] = o;
                    sm32[OUTS_B >> 2] = o;
                }
            }
        } else if (warp == 7) {
            if (lane < 28) {
                xh[nxt * 32 + lane] = __float2half_rn(xv_pre);
                int row = (t + 2 <= TST) ? (t + 2) : TST;
                xv_pre = xdec[((size_t)b * (TST + 1) + row) * DSZ + lane];
            }
        }
        __syncthreads();

        // ======== PHASE C: gates (lanes<8) + attention (all warps, head=warp) ======
        {
            if (lane < 8) {
                const int i = warp * 8 + lane;
                float o  = sm32[OUTS_B >> 2];
                float gr = sm32[(GS_B >> 2) + i]      + w28r * o;
                float gz = sm32[(GS_B >> 2) + 64 + i] + w28z * o;
                float ax = sm32[(GXN_B >> 2) + i]     + w28n * o;
                float ah = sm32[(GHN_B >> 2) + i];
                float r  = 1.f / (1.f + __expf(-gr));
                float z  = 1.f / (1.f + __expf(-gz));
                float a  = ax + r * ah;
                float e2 = __expf(2.f * a);
                float nt = 1.f - 2.f / (e2 + 1.f);
                float hp0 = sm32[(H32_B >> 2) + i];
                float hn = nt + z * (hp0 - nt);
                sm32[(H32_B >> 2) + i] = hn;
                hh[i] = __float2half_rn(hn);
            }
            __syncwarp();

            // q' = h_new @ Wk (lanes 0-7), scaled by log2(e); store to per-warp qsm
            if (lane < 8) {
                uint4 hv = *reinterpret_cast<const uint4*>(smc + HH_B + warp * 16);
                float2 h0 = __half22float2(u2h2(hv.x));
                float2 h1 = __half22float2(u2h2(hv.y));
                float2 h2v = __half22float2(u2h2(hv.z));
                float2 h3 = __half22float2(u2h2(hv.w));
                float q = h0.x * wk[0];
                q = fmaf(h0.y, wk[1], q);
                q = fmaf(h1.x, wk[2], q);
                q = fmaf(h1.y, wk[3], q);
                q = fmaf(h2v.x, wk[4], q);
                q = fmaf(h2v.y, wk[5], q);
                q = fmaf(h3.x, wk[6], q);
                q = fmaf(h3.y, wk[7], q);
                qsm[warp * 8 + lane] = __float2half_rn(q * 1.44269504f);
            }
            __syncwarp();
            uint4 qv = *reinterpret_cast<const uint4*>(smc + QH_B + warp * 16);
            __half2 qh[4] = { u2h2(qv.x), u2h2(qv.y), u2h2(qv.z), u2h2(qv.w) };

            // single-pass attention over swizzled fp16 val (fp16 accumulation, exp2)
            float w0 = 0.f, w1s = 0.f;
            __half2 hz = __floats2half2_rn(0.f, 0.f);
            __half2 c0 = hz, c1 = hz, c2h = hz, c3 = hz;
            const char* vb = smc + VAL_B + ((warp ^ (lane & 7)) << 4) + lane * 128;
#pragma unroll
            for (int i = 0; i < 9; ++i) {
                uint4 vv = *reinterpret_cast<const uint4*>(vb + i * 4096);
                __half2 v0 = u2h2(vv.x), v1 = u2h2(vv.y), v2 = u2h2(vv.z), v3 = u2h2(vv.w);
                __half2 s = __hmul2(qh[0], v0);
                s = __hfma2(qh[1], v1, s);
                s = __hfma2(qh[2], v2, s);
                s = __hfma2(qh[3], v3, s);
                float2 sf = __half22float2(s);
                float e = exp2f(sf.x + sf.y);
                if (i & 1) w1s += e; else w0 += e;
                __half2 eh = __float2half2_rn(e);
                c0 = __hfma2(eh, v0, c0);
                c1 = __hfma2(eh, v1, c1);
                c2h = __hfma2(eh, v2, c2h);
                c3 = __hfma2(eh, v3, c3);
            }
            float wsum = w0 + w1s;
            float2 d0 = __half22float2(c0), d1 = __half22float2(c1);
            float2 d2 = __half22float2(c2h), d3 = __half22float2(c3);
            u64 c2[4] = { pk2(d0.x, d0.y), pk2(d1.x, d1.y),
                          pk2(d2.x, d2.y), pk2(d3.x, d3.y) };

            // --- 14-shfl value-halving reduction ---
            {
                const bool hi = (lane & 16);
                u64 s0 = hi ? c2[0] : c2[2];
                u64 s1 = hi ? c2[1] : c2[3];
                u64 r0 = shfl_u64(s0, 16);
                u64 r1 = shfl_u64(s1, 16);
                u64 k0 = hi ? c2[2] : c2[0];
                u64 k1 = hi ? c2[3] : c2[1];
                c2[0] = fadd2(k0, r0);
                c2[1] = fadd2(k1, r1);
                wsum += __shfl_xor_sync(FULL, wsum, 16);
            }
            {
                const bool hi = (lane & 8);
                u64 s = hi ? c2[0] : c2[1];
                u64 r = shfl_u64(s, 8);
                u64 k = hi ? c2[1] : c2[0];
                c2[0] = fadd2(k, r);
                wsum += __shfl_xor_sync(FULL, wsum, 8);
            }
            float cv;
            {
                float lo, hi2; upk2(c2[0], lo, hi2);
                const bool hi = (lane & 4);
                float s = hi ? lo : hi2;
                float r = __shfl_xor_sync(FULL, s, 4);
                cv = (hi ? hi2 : lo) + r;
                wsum += __shfl_xor_sync(FULL, wsum, 4);
            }
            cv   += __shfl_xor_sync(FULL, cv, 2);
            wsum += __shfl_xor_sync(FULL, wsum, 2);
            cv   += __shfl_xor_sync(FULL, cv, 1);
            wsum += __shfl_xor_sync(FULL, wsum, 1);
            if ((lane & 3) == 0)
                ctxh[warp * 8 + (lane >> 2)] = __float2half_rn(cv * (1.f / wsum));
        }
        __syncthreads();
    }

    // final output MLP (step TST-1)
    if (warp == 6) {
        const int sw = lane & 7;
        const char* wrow = smc + W1_B + lane * 128;
        __half2 a0 = __floats2half2_rn(0.f, 0.f), a1 = a0, a2 = a0, a3 = a0;
#pragma unroll
        for (int k = 0; k < 8; ++k) {
            uint4 wv = *reinterpret_cast<const uint4*>(wrow + ((k ^ sw) << 4));
            uint4 cv = *reinterpret_cast<const uint4*>(smc + CTXH_B + (k << 4));
            a0 = __hfma2(u2h2(wv.x), u2h2(cv.x), a0);
            a1 = __hfma2(u2h2(wv.y), u2h2(cv.y), a1);
            a2 = __hfma2(u2h2(wv.z), u2h2(cv.z), a2);
            a3 = __hfma2(u2h2(wv.w), u2h2(cv.w), a3);
        }
        float2 f0 = __half22float2(a0), f1 = __half22float2(a1);
        float2 f2 = __half22float2(a2), f3 = __half22float2(a3);
        float y = ba + ((f0.x + f0.y) + (f1.x + f1.y)) + ((f2.x + f2.y) + (f3.x + f3.y));
        float p = fmaxf(y, 0.f) * bb;
#pragma unroll
        for (int off = 16; off >= 1; off >>= 1)
            p += __shfl_xor_sync(FULL, p, off);
        if (lane == 0)
            out[(size_t)b * TST + (TST - 1)] = p + b2r;
    }
}

extern "C" void kernel_launch(void* const* d_in, const int* in_sizes, int n_in,
                              void* d_out, int out_size)
{
    const float* xdec = (const float*)d_in[0];
    const float* enc  = (const float*)d_in[1];
    const float* hidp = (const float*)d_in[2];
    const float* Wih  = (const float*)d_in[3];
    const float* Whh  = (const float*)d_in[4];
    const float* bih  = (const float*)d_in[5];
    const float* bhh  = (const float*)d_in[6];
    const float* Wk   = (const float*)d_in[7];
    const float* bk   = (const float*)d_in[8];
    const float* W1   = (const float*)d_in[9];
    const float* b1   = (const float*)d_in[10];
    const float* W2   = (const float*)d_in[11];
    const float* b2   = (const float*)d_in[12];
    float* out = (float*)d_out;

    cudaFuncSetAttribute(decoder_persist_kernel,
                         cudaFuncAttributeMaxDynamicSharedMemorySize, SMEM_BYTES);
    decoder_persist_kernel<<<BS, NTHR, SMEM_BYTES>>>(xdec, enc, hidp, Wih, Whh, bih, bhh,
                                                     Wk, bk, W1, b1, W2, b2, out);
}